// round 3
// baseline (speedup 1.0000x reference)
#include <cuda_runtime.h>
#include <math.h>

// Problem-shape constants
#define NN     50000
#define EE     800000
#define ETMAX  (EE + NN)
#define INC    128
#define HEADS  3
#define HID    64
#define H1DIM  (HEADS * HID) // 192
#define OUTC   64

#define NEG_SLOPE 0.2f
#define EPSF 1e-16f

// ---------------- scratch (static device globals; no allocations) ----------------
__device__ float g_h1  [(size_t)NN * H1DIM];
__device__ float g_out1[(size_t)NN * H1DIM];
__device__ float g_as1 [NN * HEADS];
__device__ float g_ad1 [NN * HEADS];
__device__ float g_e1  [(size_t)ETMAX * HEADS];
__device__ float g_max1[NN * HEADS];
__device__ float g_sum1[NN * HEADS];
__device__ float g_h2  [(size_t)NN * OUTC];
__device__ float g_as2 [NN];
__device__ float g_ad2 [NN];
__device__ float g_e2  [ETMAX];
__device__ float g_max2[NN];
__device__ float g_sum2[NN];

// ---------------- helpers ----------------
__device__ __forceinline__ void atomicMaxF(float* addr, float val) {
    if (val >= 0.0f) atomicMax((int*)addr, __float_as_int(val));
    else             atomicMin((unsigned int*)addr, __float_as_uint(val));
}

__device__ __forceinline__ void edge_endpoints(const int* __restrict__ ei, int idx,
                                               int e_real, int& src, int& dst) {
    if (idx < e_real) { src = ei[idx]; dst = ei[e_real + idx]; }
    else              { src = idx - e_real; dst = src; }
}

__device__ __forceinline__ void atomicAddF4(float4* addr, float4 v) {
#if (__CUDA_ARCH__ >= 900) && (CUDART_VERSION >= 12080)
    atomicAdd(addr, v);
#else
    float* p = (float*)addr;
    atomicAdd(p + 0, v.x); atomicAdd(p + 1, v.y);
    atomicAdd(p + 2, v.z); atomicAdd(p + 3, v.w);
#endif
}

// ---------------- init ----------------
__global__ void k_init(float* __restrict__ out1, float* __restrict__ out,
                       float* __restrict__ sum1, float* __restrict__ max1,
                       float* __restrict__ sum2, float* __restrict__ max2,
                       int n, int out_elems) {
    int i = blockIdx.x * blockDim.x + threadIdx.x;
    int tot = n * H1DIM;
    if (i < tot)        out1[i] = 0.0f;
    if (i < out_elems)  out[i]  = 0.0f;
    if (i < n * HEADS)  { sum1[i] = 0.0f; max1[i] = -INFINITY; }
    if (i < n)          { sum2[i] = 0.0f; max2[i] = -INFINITY; }
}

// ---------------- tiled fp32 GEMM: C[M,N] = A[M,K] @ B[K,N] ----------------
// BM=BN=64, BK=16, 256 threads, 4x4 per thread.
__global__ void k_gemm(const float* __restrict__ A, const float* __restrict__ B,
                       float* __restrict__ C, int M, int N, int K) {
    __shared__ float As[16][64];
    __shared__ float Bs[16][68];

    int tid = threadIdx.x;
    int tx = tid % 16, ty = tid / 16;
    int m0 = blockIdx.y * 64;
    int n0 = blockIdx.x * 64;

    float acc[4][4];
    #pragma unroll
    for (int i = 0; i < 4; i++)
        #pragma unroll
        for (int j = 0; j < 4; j++) acc[i][j] = 0.0f;

    for (int k0 = 0; k0 < K; k0 += 16) {
        #pragma unroll
        for (int l = tid; l < 64 * 16; l += 256) {
            int row = l >> 4, kk = l & 15;
            int gm = m0 + row;
            As[kk][row] = (gm < M) ? A[(size_t)gm * K + k0 + kk] : 0.0f;
        }
        #pragma unroll
        for (int l = tid; l < 16 * 64; l += 256) {
            int kk = l >> 6, col = l & 63;
            int gn = n0 + col;
            Bs[kk][col] = (gn < N) ? B[(size_t)(k0 + kk) * N + gn] : 0.0f;
        }
        __syncthreads();

        #pragma unroll
        for (int kk = 0; kk < 16; kk++) {
            float a[4], b[4];
            #pragma unroll
            for (int i = 0; i < 4; i++) a[i] = As[kk][ty * 4 + i];
            #pragma unroll
            for (int j = 0; j < 4; j++) b[j] = Bs[kk][tx * 4 + j];
            #pragma unroll
            for (int i = 0; i < 4; i++)
                #pragma unroll
                for (int j = 0; j < 4; j++) acc[i][j] = fmaf(a[i], b[j], acc[i][j]);
        }
        __syncthreads();
    }

    #pragma unroll
    for (int i = 0; i < 4; i++) {
        int gm = m0 + ty * 4 + i;
        if (gm >= M) continue;
        #pragma unroll
        for (int j = 0; j < 4; j++) {
            int gn = n0 + tx * 4 + j;
            if (gn < N) C[(size_t)gm * N + gn] = acc[i][j];
        }
    }
}

// ---------------- per-node attention logits, layer 1 (warp per (node,head)) ----
__global__ void k_att1(const float* __restrict__ h1,
                       const float* __restrict__ att_src, const float* __restrict__ att_dst,
                       float* __restrict__ as1, float* __restrict__ ad1, int n) {
    int wg = blockIdx.x * (blockDim.x / 32) + (threadIdx.x >> 5);
    int lane = threadIdx.x & 31;
    if (wg >= n * HEADS) return;
    int node = wg / HEADS, h = wg % HEADS;
    const float* hp = &h1[(size_t)node * H1DIM + h * HID];
    float v0 = hp[lane], v1 = hp[lane + 32];
    float s = v0 * att_src[h * HID + lane] + v1 * att_src[h * HID + lane + 32];
    float d = v0 * att_dst[h * HID + lane] + v1 * att_dst[h * HID + lane + 32];
    #pragma unroll
    for (int o = 16; o > 0; o >>= 1) {
        s += __shfl_down_sync(0xffffffff, s, o);
        d += __shfl_down_sync(0xffffffff, d, o);
    }
    if (lane == 0) { as1[node * HEADS + h] = s; ad1[node * HEADS + h] = d; }
}

// ---------------- edge pass A (layer1): logit + leaky_relu + segment max ------
__global__ void k_edgemax1(const int* __restrict__ ei,
                           const float* __restrict__ as1, const float* __restrict__ ad1,
                           float* __restrict__ e1, float* __restrict__ max1,
                           int e_real, int et) {
    int i = blockIdx.x * blockDim.x + threadIdx.x;
    if (i >= et * HEADS) return;
    int edge = i / HEADS, h = i % HEADS;
    int src, dst; edge_endpoints(ei, edge, e_real, src, dst);
    float l = as1[src * HEADS + h] + ad1[dst * HEADS + h];
    float e = (l > 0.0f) ? l : NEG_SLOPE * l;
    e1[i] = e;
    atomicMaxF(&max1[dst * HEADS + h], e);
}

// ---------------- edge pass B (layer1): exp + segment sum ---------------------
__global__ void k_edgeexp1(const int* __restrict__ ei,
                           float* __restrict__ e1,
                           const float* __restrict__ max1, float* __restrict__ sum1,
                           int e_real, int et) {
    int i = blockIdx.x * blockDim.x + threadIdx.x;
    if (i >= et * HEADS) return;
    int edge = i / HEADS, h = i % HEADS;
    int src, dst; edge_endpoints(ei, edge, e_real, src, dst);
    float ex = expf(e1[i] - max1[dst * HEADS + h]);
    e1[i] = ex;
    atomicAdd(&sum1[dst * HEADS + h], ex);
}

// ---------------- edge pass C (layer1): weighted scatter aggregate ------------
// flat index: thread = (edge, chunk), chunk covers 4 channels. 48 chunks/edge.
__global__ void k_agg1(const int* __restrict__ ei,
                       const float* __restrict__ h1, const float* __restrict__ e1,
                       const float* __restrict__ sum1, float* __restrict__ out1,
                       int e_real, int et) {
    int i = blockIdx.x * blockDim.x + threadIdx.x;
    if (i >= et * 48) return;
    int edge = i / 48, c4 = i % 48;
    int h = c4 >> 4;                 // (c4*4)/64
    int src, dst; edge_endpoints(ei, edge, e_real, src, dst);
    float alpha = e1[(size_t)edge * HEADS + h] / (sum1[dst * HEADS + h] + EPSF);
    float4 v = ((const float4*)&h1[(size_t)src * H1DIM])[c4];
    v.x *= alpha; v.y *= alpha; v.z *= alpha; v.w *= alpha;
    atomicAddF4(&((float4*)&out1[(size_t)dst * H1DIM])[c4], v);
}

// ---------------- bias + ELU (in place) ---------------------------------------
__global__ void k_act1(float* __restrict__ out1, const float* __restrict__ b1, int n) {
    int i = blockIdx.x * blockDim.x + threadIdx.x;
    if (i >= n * H1DIM) return;
    float v = out1[i] + b1[i % H1DIM];
    out1[i] = (v > 0.0f) ? v : expm1f(v);
}

// ---------------- per-node attention logits, layer 2 (warp per node) ----------
__global__ void k_att2(const float* __restrict__ h2,
                       const float* __restrict__ att_src, const float* __restrict__ att_dst,
                       float* __restrict__ as2, float* __restrict__ ad2, int n) {
    int node = blockIdx.x * (blockDim.x / 32) + (threadIdx.x >> 5);
    int lane = threadIdx.x & 31;
    if (node >= n) return;
    const float* hp = &h2[(size_t)node * OUTC];
    float v0 = hp[lane], v1 = hp[lane + 32];
    float s = v0 * att_src[lane] + v1 * att_src[lane + 32];
    float d = v0 * att_dst[lane] + v1 * att_dst[lane + 32];
    #pragma unroll
    for (int o = 16; o > 0; o >>= 1) {
        s += __shfl_down_sync(0xffffffff, s, o);
        d += __shfl_down_sync(0xffffffff, d, o);
    }
    if (lane == 0) { as2[node] = s; ad2[node] = d; }
}

__global__ void k_edgemax2(const int* __restrict__ ei,
                           const float* __restrict__ as2, const float* __restrict__ ad2,
                           float* __restrict__ e2, float* __restrict__ max2,
                           int e_real, int et) {
    int edge = blockIdx.x * blockDim.x + threadIdx.x;
    if (edge >= et) return;
    int src, dst; edge_endpoints(ei, edge, e_real, src, dst);
    float l = as2[src] + ad2[dst];
    float e = (l > 0.0f) ? l : NEG_SLOPE * l;
    e2[edge] = e;
    atomicMaxF(&max2[dst], e);
}

__global__ void k_edgeexp2(const int* __restrict__ ei,
                           float* __restrict__ e2,
                           const float* __restrict__ max2, float* __restrict__ sum2,
                           int e_real, int et) {
    int edge = blockIdx.x * blockDim.x + threadIdx.x;
    if (edge >= et) return;
    int src, dst; edge_endpoints(ei, edge, e_real, src, dst);
    float ex = expf(e2[edge] - max2[dst]);
    e2[edge] = ex;
    atomicAdd(&sum2[dst], ex);
}

// flat index: thread = (edge, chunk), 16 float4 chunks per edge
__global__ void k_agg2(const int* __restrict__ ei,
                       const float* __restrict__ h2, const float* __restrict__ e2,
                       const float* __restrict__ sum2, float* __restrict__ out,
                       int e_real, int et) {
    int i = blockIdx.x * blockDim.x + threadIdx.x;
    if (i >= et * 16) return;
    int edge = i >> 4, c4 = i & 15;
    int src, dst; edge_endpoints(ei, edge, e_real, src, dst);
    float alpha = e2[edge] / (sum2[dst] + EPSF);
    float4 v = ((const float4*)&h2[(size_t)src * OUTC])[c4];
    v.x *= alpha; v.y *= alpha; v.z *= alpha; v.w *= alpha;
    atomicAddF4(&((float4*)&out[(size_t)dst * OUTC])[c4], v);
}

__global__ void k_bias2(float* __restrict__ out, const float* __restrict__ b2, int n) {
    int i = blockIdx.x * blockDim.x + threadIdx.x;
    if (i >= n * OUTC) return;
    out[i] += b2[i & 63];
}

// ---------------- launcher ----------------
extern "C" void kernel_launch(void* const* d_in, const int* in_sizes, int n_in,
                              void* d_out, int out_size) {
    // Resolve device addresses of __device__ scratch symbols. (Passing the
    // symbol directly from host code passes the host shadow address ->
    // illegal access; this API lookup is the fix, and is capture-safe.)
    float *p_h1, *p_out1, *p_as1, *p_ad1, *p_e1, *p_max1, *p_sum1;
    float *p_h2, *p_as2, *p_ad2, *p_e2, *p_max2, *p_sum2;
    cudaGetSymbolAddress((void**)&p_h1,   g_h1);
    cudaGetSymbolAddress((void**)&p_out1, g_out1);
    cudaGetSymbolAddress((void**)&p_as1,  g_as1);
    cudaGetSymbolAddress((void**)&p_ad1,  g_ad1);
    cudaGetSymbolAddress((void**)&p_e1,   g_e1);
    cudaGetSymbolAddress((void**)&p_max1, g_max1);
    cudaGetSymbolAddress((void**)&p_sum1, g_sum1);
    cudaGetSymbolAddress((void**)&p_h2,   g_h2);
    cudaGetSymbolAddress((void**)&p_as2,  g_as2);
    cudaGetSymbolAddress((void**)&p_ad2,  g_ad2);
    cudaGetSymbolAddress((void**)&p_e2,   g_e2);
    cudaGetSymbolAddress((void**)&p_max2, g_max2);
    cudaGetSymbolAddress((void**)&p_sum2, g_sum2);

    // Robust input mapping by element count (appearance order within class).
    const float* x = nullptr; const int* ei = nullptr;
    const float* W1 = nullptr; const float* W2 = nullptr;
    const float* s192[3] = {nullptr, nullptr, nullptr}; int n192 = 0;
    const float* s64 [3] = {nullptr, nullptr, nullptr}; int n64  = 0;
    for (int i = 0; i < n_in; i++) {
        int sz = in_sizes[i];
        if      (sz == NN * INC)        x  = (const float*)d_in[i];
        else if (sz == 2 * EE)          ei = (const int*)  d_in[i];
        else if (sz == INC * H1DIM)     W1 = (const float*)d_in[i];
        else if (sz == H1DIM * OUTC)    W2 = (const float*)d_in[i];
        else if (sz == H1DIM && n192 < 3) s192[n192++] = (const float*)d_in[i];
        else if (sz == OUTC  && n64  < 3) s64 [n64++]  = (const float*)d_in[i];
    }
    const float* att_src1 = s192[0]; const float* att_dst1 = s192[1]; const float* b1 = s192[2];
    const float* att_src2 = s64[0];  const float* att_dst2 = s64[1];  const float* b2 = s64[2];

    float* out = (float*)d_out;
    int n  = NN;
    int e  = EE;
    int et = e + n;

    // init
    {
        int tot = n * H1DIM;
        k_init<<<(tot + 255) / 256, 256>>>(p_out1, out, p_sum1, p_max1, p_sum2, p_max2,
                                           n, out_size);
    }

    // layer 1
    {
        dim3 grid((H1DIM + 63) / 64, (n + 63) / 64);
        k_gemm<<<grid, 256>>>(x, W1, p_h1, n, H1DIM, INC);
    }
    {
        int warps = n * HEADS;
        k_att1<<<(warps + 3) / 4, 128>>>(p_h1, att_src1, att_dst1, p_as1, p_ad1, n);
    }
    {
        int tot = et * HEADS;
        k_edgemax1<<<(tot + 255) / 256, 256>>>(ei, p_as1, p_ad1, p_e1, p_max1, e, et);
        k_edgeexp1<<<(tot + 255) / 256, 256>>>(ei, p_e1, p_max1, p_sum1, e, et);
    }
    {
        long long tot = (long long)et * 48;
        k_agg1<<<(int)((tot + 255) / 256), 256>>>(ei, p_h1, p_e1, p_sum1, p_out1, e, et);
    }
    {
        int tot = n * H1DIM;
        k_act1<<<(tot + 255) / 256, 256>>>(p_out1, b1, n);
    }

    // layer 2
    {
        dim3 grid((OUTC + 63) / 64, (n + 63) / 64);
        k_gemm<<<grid, 256>>>(p_out1, W2, p_h2, n, OUTC, H1DIM);
    }
    k_att2<<<(n + 3) / 4, 128>>>(p_h2, att_src2, att_dst2, p_as2, p_ad2, n);
    k_edgemax2<<<(et + 255) / 256, 256>>>(ei, p_as2, p_ad2, p_e2, p_max2, e, et);
    k_edgeexp2<<<(et + 255) / 256, 256>>>(ei, p_e2, p_max2, p_sum2, e, et);
    {
        long long tot = (long long)et * 16;
        k_agg2<<<(int)((tot + 255) / 256), 256>>>(ei, p_h2, p_e2, p_sum2, out, e, et);
    }
    k_bias2<<<(n * OUTC + 255) / 256, 256>>>(out, b2, n);
}

// round 4
// speedup vs baseline: 1.8019x; 1.8019x over previous
#include <cuda_runtime.h>
#include <math.h>

#define NN     50000
#define EE     800000
#define ETMAX  (EE + NN)
#define INC    128
#define HEADS  3
#define HID    64
#define H1DIM  (HEADS * HID) // 192
#define OUTC   64

#define NEG_SLOPE 0.2f
#define EPSF 1e-16f

// ---------------- scratch (static device globals; no allocations) -------------
__device__ float g_h1  [(size_t)NN * H1DIM];   // x @ W1
__device__ float g_out1[(size_t)NN * H1DIM];   // layer1 output (post ELU)
__device__ float g_h2  [(size_t)NN * OUTC];    // out1 @ W2
__device__ float g_as1 [NN * HEADS];
__device__ float g_ad1 [NN * HEADS];
__device__ float g_as2 [NN];
__device__ float g_ad2 [NN];
__device__ int   g_deg   [NN];
__device__ int   g_cursor[NN];
__device__ int   g_off   [NN + 1];
__device__ int   g_elist [ETMAX];   // src node per CSR slot (dst-bucketed)

// ---------------- init: zero CSR counters ------------------------------------
__global__ void k_init(int* __restrict__ deg, int* __restrict__ cur, int n) {
    int i = blockIdx.x * blockDim.x + threadIdx.x;
    if (i < n) { deg[i] = 0; cur[i] = 0; }
}

// ---------------- CSR build ---------------------------------------------------
__global__ void k_hist(const int* __restrict__ ei, int* __restrict__ deg,
                       int e_real, int et) {
    int i = blockIdx.x * blockDim.x + threadIdx.x;
    if (i >= et) return;
    int dst = (i < e_real) ? ei[e_real + i] : (i - e_real);
    atomicAdd(&deg[dst], 1);
}

// single-block exclusive scan over n=50000 (1024 threads, ~49 elems each)
__global__ void k_scan(const int* __restrict__ deg, int* __restrict__ off, int n) {
    __shared__ int part[1024];
    int t = threadIdx.x;
    int chunk = (n + 1023) / 1024;
    int b = t * chunk;
    int s = 0;
    for (int j = 0; j < chunk; j++) {
        int idx = b + j;
        if (idx < n) s += deg[idx];
    }
    part[t] = s;
    __syncthreads();
    // Hillis-Steele inclusive scan
    for (int d = 1; d < 1024; d <<= 1) {
        int v = (t >= d) ? part[t - d] : 0;
        __syncthreads();
        part[t] += v;
        __syncthreads();
    }
    int run = (t == 0) ? 0 : part[t - 1];
    for (int j = 0; j < chunk; j++) {
        int idx = b + j;
        if (idx < n) { off[idx] = run; run += deg[idx]; }
    }
    if (t == 1023) off[n] = part[1023];
}

__global__ void k_bucket(const int* __restrict__ ei, const int* __restrict__ off,
                         int* __restrict__ cur, int* __restrict__ elist,
                         int e_real, int et) {
    int i = blockIdx.x * blockDim.x + threadIdx.x;
    if (i >= et) return;
    int src, dst;
    if (i < e_real) { src = ei[i]; dst = ei[e_real + i]; }
    else            { src = i - e_real; dst = src; }
    int pos = atomicAdd(&cur[dst], 1);
    elist[off[dst] + pos] = src;
}

// ---------------- GEMM: C[M,N] = A[M,K] @ B[K,N] ------------------------------
// BM=128, BN=64, BK=16. 256 threads; each computes 8x4. float4 global loads.
__global__ void k_gemm(const float* __restrict__ A, const float* __restrict__ B,
                       float* __restrict__ C, int M, int N, int K) {
    __shared__ float As[16][129];   // pad 129: conflict-free transposed stores
    __shared__ float Bs[16][68];

    int tid = threadIdx.x;
    int tx = tid & 15;        // 0..15 -> 4 cols each
    int ty = tid >> 4;        // 0..15 -> 8 rows each
    int m0 = blockIdx.y * 128;
    int n0 = blockIdx.x * 64;

    float acc[8][4];
    #pragma unroll
    for (int i = 0; i < 8; i++)
        #pragma unroll
        for (int j = 0; j < 4; j++) acc[i][j] = 0.0f;

    for (int k0 = 0; k0 < K; k0 += 16) {
        // A tile: 128 rows x 16 k = 512 float4 slots; 2 per thread
        #pragma unroll
        for (int q = 0; q < 2; q++) {
            int slot = tid + q * 256;
            int row = slot >> 2, kq = slot & 3;
            int gm = m0 + row;
            float4 v = make_float4(0.f, 0.f, 0.f, 0.f);
            if (gm < M) v = *(const float4*)&A[(size_t)gm * K + k0 + kq * 4];
            As[kq * 4 + 0][row] = v.x;
            As[kq * 4 + 1][row] = v.y;
            As[kq * 4 + 2][row] = v.z;
            As[kq * 4 + 3][row] = v.w;
        }
        // B tile: 16 k x 64 cols = 256 float4 slots; 1 per thread
        {
            int kk = tid >> 4, col4 = (tid & 15) * 4;   // N multiples of 64: no guard
            float4 v = *(const float4*)&B[(size_t)(k0 + kk) * N + n0 + col4];
            Bs[kk][col4 + 0] = v.x;
            Bs[kk][col4 + 1] = v.y;
            Bs[kk][col4 + 2] = v.z;
            Bs[kk][col4 + 3] = v.w;
        }
        __syncthreads();

        #pragma unroll
        for (int kk = 0; kk < 16; kk++) {
            float a[8], b[4];
            #pragma unroll
            for (int i = 0; i < 8; i++) a[i] = As[kk][ty * 8 + i];
            #pragma unroll
            for (int j = 0; j < 4; j++) b[j] = Bs[kk][tx * 4 + j];
            #pragma unroll
            for (int i = 0; i < 8; i++)
                #pragma unroll
                for (int j = 0; j < 4; j++) acc[i][j] = fmaf(a[i], b[j], acc[i][j]);
        }
        __syncthreads();
    }

    #pragma unroll
    for (int i = 0; i < 8; i++) {
        int gm = m0 + ty * 8 + i;
        if (gm >= M) continue;
        float4 v = make_float4(acc[i][0], acc[i][1], acc[i][2], acc[i][3]);
        *(float4*)&C[(size_t)gm * N + n0 + tx * 4] = v;
    }
}

// ---------------- per-node attention logits ----------------------------------
__global__ void k_att1(const float* __restrict__ h1,
                       const float* __restrict__ att_src, const float* __restrict__ att_dst,
                       float* __restrict__ as1, float* __restrict__ ad1, int n) {
    int wg = blockIdx.x * (blockDim.x / 32) + (threadIdx.x >> 5);
    int lane = threadIdx.x & 31;
    if (wg >= n * HEADS) return;
    int node = wg / HEADS, h = wg % HEADS;
    const float* hp = &h1[(size_t)node * H1DIM + h * HID];
    float v0 = hp[lane], v1 = hp[lane + 32];
    float s = v0 * att_src[h * HID + lane] + v1 * att_src[h * HID + lane + 32];
    float d = v0 * att_dst[h * HID + lane] + v1 * att_dst[h * HID + lane + 32];
    #pragma unroll
    for (int o = 16; o > 0; o >>= 1) {
        s += __shfl_down_sync(0xffffffff, s, o);
        d += __shfl_down_sync(0xffffffff, d, o);
    }
    if (lane == 0) { as1[node * HEADS + h] = s; ad1[node * HEADS + h] = d; }
}

__global__ void k_att2(const float* __restrict__ h2,
                       const float* __restrict__ att_src, const float* __restrict__ att_dst,
                       float* __restrict__ as2, float* __restrict__ ad2, int n) {
    int node = blockIdx.x * (blockDim.x / 32) + (threadIdx.x >> 5);
    int lane = threadIdx.x & 31;
    if (node >= n) return;
    const float* hp = &h2[(size_t)node * OUTC];
    float v0 = hp[lane], v1 = hp[lane + 32];
    float s = v0 * att_src[lane] + v1 * att_src[lane + 32];
    float d = v0 * att_dst[lane] + v1 * att_dst[lane + 32];
    #pragma unroll
    for (int o = 16; o > 0; o >>= 1) {
        s += __shfl_down_sync(0xffffffff, s, o);
        d += __shfl_down_sync(0xffffffff, d, o);
    }
    if (lane == 0) { as2[node] = s; ad2[node] = d; }
}

// ---------------- fused GAT layer 1: warp per dst node ------------------------
// online softmax over incoming edges (3 heads), then gather-aggregate
// 192 channels -> 6 per lane. Fused bias + ELU.
__global__ void k_gat1(const int* __restrict__ elist, const int* __restrict__ off,
                       const float* __restrict__ as1, const float* __restrict__ ad1,
                       const float* __restrict__ h1, const float* __restrict__ b1,
                       float* __restrict__ out1, int n) {
    int dst = blockIdx.x * (blockDim.x / 32) + (threadIdx.x >> 5);
    int lane = threadIdx.x & 31;
    if (dst >= n) return;
    int beg = off[dst], end = off[dst + 1];

    float ad0 = ad1[dst * HEADS + 0];
    float ad1v = ad1[dst * HEADS + 1];
    float ad2v = ad1[dst * HEADS + 2];

    // pass 1: per-lane online (max, sum) per head
    float m[3] = {-INFINITY, -INFINITY, -INFINITY};
    float s[3] = {0.f, 0.f, 0.f};
    for (int i = beg + lane; i < end; i += 32) {
        int src = elist[i];
        float e0 = as1[src * HEADS + 0] + ad0;
        float e1 = as1[src * HEADS + 1] + ad1v;
        float e2 = as1[src * HEADS + 2] + ad2v;
        e0 = (e0 > 0.f) ? e0 : NEG_SLOPE * e0;
        e1 = (e1 > 0.f) ? e1 : NEG_SLOPE * e1;
        e2 = (e2 > 0.f) ? e2 : NEG_SLOPE * e2;
        float e[3] = {e0, e1, e2};
        #pragma unroll
        for (int h = 0; h < 3; h++) {
            float nm = fmaxf(m[h], e[h]);
            s[h] = s[h] * __expf(m[h] - nm) + __expf(e[h] - nm);
            m[h] = nm;
        }
    }
    // warp combine (butterfly -> all lanes hold the result)
    #pragma unroll
    for (int o = 16; o > 0; o >>= 1) {
        #pragma unroll
        for (int h = 0; h < 3; h++) {
            float m2 = __shfl_xor_sync(0xffffffff, m[h], o);
            float s2 = __shfl_xor_sync(0xffffffff, s[h], o);
            float nm = fmaxf(m[h], m2);
            float w1 = (m[h] == -INFINITY) ? 0.f : __expf(m[h] - nm);
            float w2 = (m2   == -INFINITY) ? 0.f : __expf(m2 - nm);
            s[h] = s[h] * w1 + s2 * w2;
            m[h] = nm;
        }
    }
    float inv[3];
    #pragma unroll
    for (int h = 0; h < 3; h++) inv[h] = 1.0f / (s[h] + EPSF);

    // pass 2: aggregate 6 channels per lane (c = lane + 32*k, head = c/64)
    float acc[6] = {0.f, 0.f, 0.f, 0.f, 0.f, 0.f};
    for (int i = beg; i < end; i++) {
        int src = elist[i];                    // uniform across warp
        float e0 = as1[src * HEADS + 0] + ad0;
        float e1 = as1[src * HEADS + 1] + ad1v;
        float e2 = as1[src * HEADS + 2] + ad2v;
        e0 = (e0 > 0.f) ? e0 : NEG_SLOPE * e0;
        e1 = (e1 > 0.f) ? e1 : NEG_SLOPE * e1;
        e2 = (e2 > 0.f) ? e2 : NEG_SLOPE * e2;
        float a0 = __expf(e0 - m[0]) * inv[0];
        float a1 = __expf(e1 - m[1]) * inv[1];
        float a2 = __expf(e2 - m[2]) * inv[2];
        const float* hp = &h1[(size_t)src * H1DIM];
        acc[0] = fmaf(hp[lane +   0], a0, acc[0]);
        acc[1] = fmaf(hp[lane +  32], a0, acc[1]);
        acc[2] = fmaf(hp[lane +  64], a1, acc[2]);
        acc[3] = fmaf(hp[lane +  96], a1, acc[3]);
        acc[4] = fmaf(hp[lane + 128], a2, acc[4]);
        acc[5] = fmaf(hp[lane + 160], a2, acc[5]);
    }
    // fused bias + ELU, single write
    float* op = &out1[(size_t)dst * H1DIM];
    #pragma unroll
    for (int k = 0; k < 6; k++) {
        int c = lane + 32 * k;
        float v = acc[k] + b1[c];
        op[c] = (v > 0.f) ? v : expm1f(v);
    }
}

// ---------------- fused GAT layer 2: warp per dst node (1 head, 64 ch) --------
__global__ void k_gat2(const int* __restrict__ elist, const int* __restrict__ off,
                       const float* __restrict__ as2, const float* __restrict__ ad2,
                       const float* __restrict__ h2, const float* __restrict__ b2,
                       float* __restrict__ out, int n) {
    int dst = blockIdx.x * (blockDim.x / 32) + (threadIdx.x >> 5);
    int lane = threadIdx.x & 31;
    if (dst >= n) return;
    int beg = off[dst], end = off[dst + 1];

    float ad = ad2[dst];

    float m = -INFINITY, s = 0.f;
    for (int i = beg + lane; i < end; i += 32) {
        int src = elist[i];
        float e = as2[src] + ad;
        e = (e > 0.f) ? e : NEG_SLOPE * e;
        float nm = fmaxf(m, e);
        s = s * __expf(m - nm) + __expf(e - nm);
        m = nm;
    }
    #pragma unroll
    for (int o = 16; o > 0; o >>= 1) {
        float m2 = __shfl_xor_sync(0xffffffff, m, o);
        float s2 = __shfl_xor_sync(0xffffffff, s, o);
        float nm = fmaxf(m, m2);
        float w1 = (m  == -INFINITY) ? 0.f : __expf(m - nm);
        float w2 = (m2 == -INFINITY) ? 0.f : __expf(m2 - nm);
        s = s * w1 + s2 * w2;
        m = nm;
    }
    float invs = 1.0f / (s + EPSF);

    float acc0 = 0.f, acc1 = 0.f;
    for (int i = beg; i < end; i++) {
        int src = elist[i];
        float e = as2[src] + ad;
        e = (e > 0.f) ? e : NEG_SLOPE * e;
        float a = __expf(e - m) * invs;
        const float* hp = &h2[(size_t)src * OUTC];
        acc0 = fmaf(hp[lane],      a, acc0);
        acc1 = fmaf(hp[lane + 32], a, acc1);
    }
    float* op = &out[(size_t)dst * OUTC];
    op[lane]      = acc0 + b2[lane];
    op[lane + 32] = acc1 + b2[lane + 32];
}

// ---------------- launcher ----------------
extern "C" void kernel_launch(void* const* d_in, const int* in_sizes, int n_in,
                              void* d_out, int out_size) {
    float *p_h1, *p_out1, *p_h2, *p_as1, *p_ad1, *p_as2, *p_ad2;
    int *p_deg, *p_cur, *p_off, *p_elist;
    cudaGetSymbolAddress((void**)&p_h1,    g_h1);
    cudaGetSymbolAddress((void**)&p_out1,  g_out1);
    cudaGetSymbolAddress((void**)&p_h2,    g_h2);
    cudaGetSymbolAddress((void**)&p_as1,   g_as1);
    cudaGetSymbolAddress((void**)&p_ad1,   g_ad1);
    cudaGetSymbolAddress((void**)&p_as2,   g_as2);
    cudaGetSymbolAddress((void**)&p_ad2,   g_ad2);
    cudaGetSymbolAddress((void**)&p_deg,   g_deg);
    cudaGetSymbolAddress((void**)&p_cur,   g_cursor);
    cudaGetSymbolAddress((void**)&p_off,   g_off);
    cudaGetSymbolAddress((void**)&p_elist, g_elist);

    const float* x = nullptr; const int* ei = nullptr;
    const float* W1 = nullptr; const float* W2 = nullptr;
    const float* s192[3] = {nullptr, nullptr, nullptr}; int n192 = 0;
    const float* s64 [3] = {nullptr, nullptr, nullptr}; int n64  = 0;
    for (int i = 0; i < n_in; i++) {
        int sz = in_sizes[i];
        if      (sz == NN * INC)        x  = (const float*)d_in[i];
        else if (sz == 2 * EE)          ei = (const int*)  d_in[i];
        else if (sz == INC * H1DIM)     W1 = (const float*)d_in[i];
        else if (sz == H1DIM * OUTC)    W2 = (const float*)d_in[i];
        else if (sz == H1DIM && n192 < 3) s192[n192++] = (const float*)d_in[i];
        else if (sz == OUTC  && n64  < 3) s64 [n64++]  = (const float*)d_in[i];
    }
    const float* att_src1 = s192[0]; const float* att_dst1 = s192[1]; const float* b1 = s192[2];
    const float* att_src2 = s64[0];  const float* att_dst2 = s64[1];  const float* b2 = s64[2];

    float* out = (float*)d_out;
    int n  = NN;
    int e  = EE;
    int et = e + n;

    // CSR build (shared by both layers) — overlaps conceptually with GEMM1
    k_init  <<<(n + 255) / 256, 256>>>(p_deg, p_cur, n);
    k_hist  <<<(et + 255) / 256, 256>>>(ei, p_deg, e, et);
    k_scan  <<<1, 1024>>>(p_deg, p_off, n);
    k_bucket<<<(et + 255) / 256, 256>>>(ei, p_off, p_cur, p_elist, e, et);

    // layer 1
    {
        dim3 grid(H1DIM / 64, (n + 127) / 128);
        k_gemm<<<grid, 256>>>(x, W1, p_h1, n, H1DIM, INC);
    }
    {
        int warps = n * HEADS;
        k_att1<<<(warps + 3) / 4, 128>>>(p_h1, att_src1, att_dst1, p_as1, p_ad1, n);
    }
    k_gat1<<<(n + 7) / 8, 256>>>(p_elist, p_off, p_as1, p_ad1, p_h1, b1, p_out1, n);

    // layer 2
    {
        dim3 grid(OUTC / 64, (n + 127) / 128);
        k_gemm<<<grid, 256>>>(p_out1, W2, p_h2, n, OUTC, H1DIM);
    }
    k_att2<<<(n + 3) / 4, 128>>>(p_h2, att_src2, att_dst2, p_as2, p_ad2, n);
    k_gat2<<<(n + 7) / 8, 256>>>(p_elist, p_off, p_as2, p_ad2, p_h2, b2, out, n);
}